// round 2
// baseline (speedup 1.0000x reference)
#include <cuda_runtime.h>
#include <math.h>

// ---------------------------------------------------------------------------
// CombinedLoss: 0.5*mean|o-t| + 0.5*mean|CWT(o)-CWT(t)| (real morlet, 36 widths)
// CWT(o)-CWT(t) = CWT(d), d=o-t.  'same' conv with reversed kernel ==
// correlation with un-reversed morlet:
//   conv_w[i] = sum_{p=0}^{10w-1} mor_w[p] * d[i + p - 5w]   (zero padded)
// Round 2: packed fma.rn.f32x2 (2 FMAs per fma-pipe instruction).
// ---------------------------------------------------------------------------

#define L_TOTAL   262144
#define NWIDTHS   36
#define KTOTAL    6660        // sum_{w=1..36} 10w
#define THREADS   128
#define RBLK      10          // outputs per thread; 10 | 10w for all w
#define TILE      (THREADS * RBLK)                // 1280
#define NBX       ((L_TOTAL + TILE - 1) / TILE)   // 205
#define SD_LEN    (TILE + 2 * 180)                // 1640
#define SK_LEN    1710                            // largest group tap count

typedef unsigned long long ull;

__device__ float  g_ker[KTOTAL];
__device__ double g_acc_wave;
__device__ double g_acc_cwt;

// Width-group boundaries (balanced tap counts: 1710/1540/1710/1700)
__constant__ int c_w0[4] = {1, 19, 26, 32};
__constant__ int c_w1[4] = {19, 26, 32, 37};
__constant__ int c_H [4] = {90, 126, 156, 180};   // even halos >= 5*(w1-1)

// ---------- packed f32x2 helpers ----------
__device__ __forceinline__ void ffma2(ull& d, ull a, ull b) {
    asm("fma.rn.f32x2 %0, %1, %2, %0;" : "+l"(d) : "l"(a), "l"(b));
}
__device__ __forceinline__ ull pk(float lo, float hi) {
    ull r; asm("mov.b64 %0, {%1, %2};" : "=l"(r) : "f"(lo), "f"(hi)); return r;
}
__device__ __forceinline__ float lo_f(ull v) {
    float a, b; asm("mov.b64 {%0, %1}, %2;" : "=f"(a), "=f"(b) : "l"(v)); return a;
}
__device__ __forceinline__ float hi_f(ull v) {
    float a, b; asm("mov.b64 {%0, %1}, %2;" : "=f"(a), "=f"(b) : "l"(v)); return b;
}

// ---------------------------------------------------------------------------
// Prep: morlet coefficients (fp32 transcendentals, double linspace arg) and
// zero the accumulators. Deterministic, runs every replay.
// ---------------------------------------------------------------------------
__global__ void prep_kernel() {
    int w = blockIdx.x + 1;            // 1..36
    int N = 10 * w;
    int off = 5 * w * (w - 1);
    const double TWO_PI = 6.283185307179586476925286766559;
    const float  PI_M025 = 0.75112554446494248f;  // pi^(-1/4)
    float ew = expf(-0.5f * (float)(w * w));
    double step = (2.0 * TWO_PI) / (double)(N - 1);
    for (int p = threadIdx.x; p < N; p += blockDim.x) {
        double xd = -TWO_PI + (double)p * step;
        float cw = cosf((float)((double)w * xd));
        float ee = expf((float)(-0.5 * xd * xd));
        g_ker[off + p] = (cw - ew) * ee * PI_M025;
    }
    if (blockIdx.x == 0 && threadIdx.x == 0) {
        g_acc_wave = 0.0;
        g_acc_cwt  = 0.0;
    }
}

__device__ __forceinline__ float warp_sum(float v) {
    #pragma unroll
    for (int o = 16; o > 0; o >>= 1) v += __shfl_xor_sync(0xFFFFFFFFu, v, o);
    return v;
}

// ---------------------------------------------------------------------------
// Main: blockIdx.x = output tile, blockIdx.y = width group.
// Packed sliding-window correlation. Per 2 taps: 10 FFMA2 + 2 LDS.64(coeff)
// + 2 LDS.32(refill) + ~4 lane MOVs  => fma-pipe bound at 2 FMA/cyc/SMSP.
// ---------------------------------------------------------------------------
__global__ void __launch_bounds__(THREADS)
cwt_kernel(const float* __restrict__ o, const float* __restrict__ t) {
    __shared__ __align__(8) float sd[SD_LEN];
    __shared__ __align__(8) float skd[2 * SK_LEN];   // duplicated taps (k,k)
    __shared__ float s_red[8];

    const int gy  = blockIdx.y;
    const int w0  = c_w0[gy];
    const int w1  = c_w1[gy];
    const int H   = c_H[gy];
    const int tile0 = blockIdx.x * TILE;
    const int tid = threadIdx.x;

    // Load diff with halo; fused |d| partial (group 0 only, interior only)
    const int span = TILE + 2 * H;
    float wsum = 0.f;
    for (int j = tid; j < span; j += THREADS) {
        int g = tile0 - H + j;
        float v = 0.f;
        if (g >= 0 && g < L_TOTAL) v = o[g] - t[g];
        sd[j] = v;
        if (gy == 0 && j >= H && j < H + TILE && g < L_TOTAL) wsum += fabsf(v);
    }
    // Load this group's taps, duplicated for packed broadcast
    const int koff0 = 5 * w0 * (w0 - 1);
    const int klen  = 5 * w1 * (w1 - 1) - koff0;
    for (int j = tid; j < klen; j += THREADS) {
        float k = g_ker[koff0 + j];
        skd[2 * j]     = k;
        skd[2 * j + 1] = k;
    }
    __syncthreads();

    float csum = 0.f;
    const int base = H + tid * RBLK;       // even

    for (int w = w0; w < w1; ++w) {
        const int N   = 10 * w;
        const int ko2 = 2 * (5 * w * (w - 1) - koff0);
        const int s0  = base - 5 * w;      // >= 0

        // window x[0..9] = sd[s0..s0+9]; packed even/odd views
        float x[RBLK];
        #pragma unroll
        for (int j = 0; j < RBLK; ++j) x[j] = sd[s0 + j];

        ull E[5], O[5], A[5];
        #pragma unroll
        for (int i = 0; i < 5; ++i) {
            E[i] = pk(x[2 * i], x[2 * i + 1]);
            O[i] = pk(x[2 * i + 1], x[(2 * i + 2) % RBLK]);
            A[i] = 0ULL;
        }

        for (int p = 0; p < N; p += RBLK) {
            #pragma unroll
            for (int m = 0; m < 5; ++m) {
                const int q = p + 2 * m;
                // even tap q: all-old E pairs
                ull k2e = *reinterpret_cast<const ull*>(&skd[ko2 + 2 * q]);
                #pragma unroll
                for (int j = 0; j < 5; ++j) ffma2(A[j], k2e, E[(m + j) % 5]);
                // refill slot 2m (lane .hi of O[m-1])
                float v0 = sd[s0 + q + RBLK];
                O[(m + 4) % 5] = pk(lo_f(O[(m + 4) % 5]), v0);
                // odd tap q+1: O pairs
                ull k2o = *reinterpret_cast<const ull*>(&skd[ko2 + 2 * q + 2]);
                #pragma unroll
                for (int j = 0; j < 5; ++j) ffma2(A[j], k2o, O[(m + j) % 5]);
                // refill slot 2m+1
                float v1 = sd[s0 + q + RBLK + 1];
                E[m] = pk(v0, v1);
                O[m] = pk(v1, hi_f(O[m]));
            }
        }

        const int gi0 = tile0 + tid * RBLK;
        #pragma unroll
        for (int i = 0; i < 5; ++i) {
            if (gi0 + 2 * i     < L_TOTAL) csum += fabsf(lo_f(A[i]));
            if (gi0 + 2 * i + 1 < L_TOTAL) csum += fabsf(hi_f(A[i]));
        }
    }

    // Block reduction -> double atomics (one per block)
    csum = warp_sum(csum);
    wsum = warp_sum(wsum);
    const int lane = tid & 31, wrp = tid >> 5;
    if (lane == 0) { s_red[wrp] = csum; s_red[4 + wrp] = wsum; }
    __syncthreads();
    if (tid == 0) {
        float c = s_red[0] + s_red[1] + s_red[2] + s_red[3];
        atomicAdd(&g_acc_cwt, (double)c);
        if (gy == 0) {
            float wv = s_red[4] + s_red[5] + s_red[6] + s_red[7];
            atomicAdd(&g_acc_wave, (double)wv);
        }
    }
}

__global__ void finalize_kernel(float* out) {
    double lw = g_acc_wave / (double)L_TOTAL;
    double lc = g_acc_cwt  / ((double)NWIDTHS * (double)L_TOTAL);
    out[0] = (float)(0.5 * lw + 0.5 * lc);
}

extern "C" void kernel_launch(void* const* d_in, const int* in_sizes, int n_in,
                              void* d_out, int out_size) {
    const float* o = (const float*)d_in[0];
    const float* t = (const float*)d_in[1];
    float* out = (float*)d_out;

    prep_kernel<<<NWIDTHS, 64>>>();
    dim3 grid(NBX, 4);
    cwt_kernel<<<grid, THREADS>>>(o, t);
    finalize_kernel<<<1, 1>>>(out);
}